// round 8
// baseline (speedup 1.0000x reference)
#include <cuda_runtime.h>

// ---------------- problem constants ----------------
#define GD 32
#define GH 512
#define GW 512
#define GRID_VOX (GD * GH * GW)
#define NMAX 151552
#define MAXP 8192
#define CH 128
#define W2Q (27 * CH * CH / 4)

// ---------------- static device scratch (zero-initialized at load) ----------------
__device__ int   g_grid[GRID_VOX];          // voxel -> active index + 1 (0 = empty)
__device__ float g_h[NMAX * CH];            // layer-1 output (tf32-rounded)
__device__ int   g_cnt[27];
__device__ int   g_pin[27 * MAXP];
__device__ int   g_pout[27 * MAXP];
__device__ int   g_in_cnt[NMAX];
__device__ int   g_in[NMAX * 26];
__device__ float g_w2t[27 * CH * CH];       // tf32-rounded w2

// ---------------- helpers ----------------
__device__ __forceinline__ float tf(float x) {
    unsigned u;
    asm("cvt.rna.tf32.f32 %0, %1;" : "=r"(u) : "f"(x));
    return __uint_as_float(u);
}
__device__ __forceinline__ void mma_tf32(float* d, const unsigned* a, const unsigned* b) {
    asm volatile(
        "mma.sync.aligned.m16n8k8.row.col.f32.tf32.tf32.f32 "
        "{%0,%1,%2,%3},{%4,%5,%6,%7},{%8,%9},{%0,%1,%2,%3};"
        : "+f"(d[0]), "+f"(d[1]), "+f"(d[2]), "+f"(d[3])
        : "r"(a[0]), "r"(a[1]), "r"(a[2]), "r"(a[3]), "r"(b[0]), "r"(b[1]));
}
__device__ __forceinline__ void cp16(void* dst, const void* src, bool pred) {
    unsigned d = (unsigned)__cvta_generic_to_shared(dst);
    int sz = pred ? 16 : 0;
    asm volatile("cp.async.cg.shared.global [%0], [%1], 16, %2;\n"
                 :: "r"(d), "l"(src), "r"(sz));
}
#define CP_COMMIT() asm volatile("cp.async.commit_group;\n")
#define CP_WAIT0()  asm volatile("cp.async.wait_group 0;\n")
__device__ __forceinline__ void red2(float* addr, float a, float b) {
    asm volatile("red.global.add.v2.f32 [%0], {%1,%2};" :: "l"(addr), "f"(a), "f"(b) : "memory");
}

// ---------------- 1) scatter + w2 tf32 convert (merged) ----------------
__global__ void k_scatter_cvt(const int* __restrict__ coors,
                              const float* __restrict__ w2, int n) {
    int i = blockIdx.x * blockDim.x + threadIdx.x;
    if (i < n) {
        int4 c = ((const int4*)coors)[i];    // (batch, z, y, x)
        g_grid[(c.y * GH + c.z) * GW + c.w] = i + 1;
    }
    if (i < W2Q) {
        float4 v = ((const float4*)w2)[i];
        v.x = tf(v.x); v.y = tf(v.y); v.z = tf(v.z); v.w = tf(v.w);
        ((float4*)g_w2t)[i] = v;
    }
}

// ---------------- 2) rulebook: one thread per point, warp-agg atomics ----------------
__global__ void k_build(const int* __restrict__ coors, int n) {
    int nn = blockIdx.x * blockDim.x + threadIdx.x;
    bool act = (nn < n);
    int4 c = make_int4(0, 0, 0, 0);
    if (act) c = ((const int4*)coors)[nn];
    int lane = threadIdx.x & 31;
    int s = 0;
#pragma unroll
    for (int k = 0; k < 27; k++) {
        if (k == 13) continue;
        const int dz = k / 9 - 1, dy = (k / 3) % 3 - 1, dx = k % 3 - 1;
        int z = c.y + dz, y = c.z + dy, x = c.w + dx;
        int m = -1;
        if (act && (unsigned)z < GD && (unsigned)y < GH && (unsigned)x < GW)
            m = g_grid[(z * GH + y) * GW + x] - 1;
        bool valid = (m >= 0);
        unsigned mask = __ballot_sync(0xffffffffu, valid);
        if (mask) {
            int leader = __ffs(mask) - 1;
            int basec = 0;
            if (lane == leader) basec = atomicAdd(&g_cnt[k], __popc(mask));
            basec = __shfl_sync(0xffffffffu, basec, leader);
            if (valid) {
                int pos = basec + __popc(mask & ((1u << lane) - 1u));
                if (pos < MAXP) {
                    g_pin [k * MAXP + pos] = m;
                    g_pout[k * MAXP + pos] = nn;
                }
                g_in[nn * 26 + s] = (k << 18) | m;
                s++;
            }
        }
    }
    if (act) g_in_cnt[nn] = s;
}

// ---------------- 3) layer1 fused gather: 32 threads/point, 4 ch each ----------------
__global__ void k_l1_fused(const float* __restrict__ feat,
                           const float* __restrict__ w1, int n) {
    int gt = blockIdx.x * blockDim.x + threadIdx.x;
    int nn = gt >> 5;
    if (nn >= n) return;
    int c = (gt & 31) * 4;

    float f0 = feat[nn * 3 + 0];
    float f1 = feat[nn * 3 + 1];
    float f2 = feat[nn * 3 + 2];
    const float* wc = w1 + 13 * 3 * CH;
    float4 r0 = *(const float4*)(wc + c);
    float4 r1 = *(const float4*)(wc + CH + c);
    float4 r2 = *(const float4*)(wc + 2 * CH + c);
    float4 acc;
    acc.x = f0 * r0.x + f1 * r1.x + f2 * r2.x;
    acc.y = f0 * r0.y + f1 * r1.y + f2 * r2.y;
    acc.z = f0 * r0.z + f1 * r1.z + f2 * r2.z;
    acc.w = f0 * r0.w + f1 * r1.w + f2 * r2.w;

    int cnt = g_in_cnt[nn];
    for (int s = 0; s < cnt; s++) {
        int packed = g_in[nn * 26 + s];
        int k = packed >> 18;
        int m = packed & 0x3FFFF;
        float g0 = feat[m * 3 + 0];
        float g1 = feat[m * 3 + 1];
        float g2 = feat[m * 3 + 2];
        const float* w = w1 + k * 3 * CH;
        float4 q0 = *(const float4*)(w + c);
        float4 q1 = *(const float4*)(w + CH + c);
        float4 q2 = *(const float4*)(w + 2 * CH + c);
        acc.x += g0 * q0.x + g1 * q1.x + g2 * q2.x;
        acc.y += g0 * q0.y + g1 * q1.y + g2 * q2.y;
        acc.z += g0 * q0.z + g1 * q1.z + g2 * q2.z;
        acc.w += g0 * q0.w + g1 * q1.w + g2 * q2.w;
    }
    acc.x = tf(acc.x); acc.y = tf(acc.y); acc.z = tf(acc.z); acc.w = tf(acc.w);
    *(float4*)(g_h + nn * CH + c) = acc;
}

// ---------------- 4) layer2 center GEMM: 128x128, 512 thr, single-sync pipeline ----------------
__global__ __launch_bounds__(512, 2) void k_center_mma(float* __restrict__ out, int n) {
    __shared__ float As[2][128][20];
    __shared__ float Bs[2][16][132];
    const float* B = g_w2t + 13 * CH * CH;
    int t = threadIdx.x;
    int wid = t >> 5, lane = t & 31;
    int wm = (wid >> 2) * 32, wn = (wid & 3) * 32;
    int lr = lane >> 2, lc = lane & 3;
    int base = blockIdx.x * 128;
    float acc[2][4][4];
#pragma unroll
    for (int i = 0; i < 2; i++)
#pragma unroll
        for (int j = 0; j < 4; j++)
#pragma unroll
            for (int q = 0; q < 4; q++) acc[i][j][q] = 0.f;

    auto stage = [&](int s, int kt) {
        {   // A: 128 rows x 16 k = 512 float4, 1 per thread
            int row = t >> 2, c4 = t & 3;
            int gr = base + row;
            cp16(&As[s][row][c4 * 4], g_h + gr * CH + kt * 16 + c4 * 4, gr < n);
        }
        {   // B: 16 k x 128 cols = 512 float4, 1 per thread
            int row = t >> 5, c4 = t & 31;
            cp16(&Bs[s][row][c4 * 4], B + (kt * 16 + row) * CH + c4 * 4, true);
        }
    };

    stage(0, 0);
    CP_COMMIT();
#pragma unroll 1
    for (int kt = 0; kt < 8; kt++) {
        int s = kt & 1;
        CP_WAIT0();
        __syncthreads();                       // publish stage(kt); all warps past mma(kt-1)
        if (kt + 1 < 8) { stage(s ^ 1, kt + 1); CP_COMMIT(); }
#pragma unroll
        for (int k8 = 0; k8 < 2; k8++) {
            unsigned a[2][4];
#pragma unroll
            for (int i = 0; i < 2; i++) {
                int r0 = wm + i * 16 + lr;
                a[i][0] = __float_as_uint(As[s][r0][k8 * 8 + lc]);
                a[i][1] = __float_as_uint(As[s][r0 + 8][k8 * 8 + lc]);
                a[i][2] = __float_as_uint(As[s][r0][k8 * 8 + lc + 4]);
                a[i][3] = __float_as_uint(As[s][r0 + 8][k8 * 8 + lc + 4]);
            }
#pragma unroll
            for (int j = 0; j < 4; j++) {
                unsigned b[2];
                int col = wn + j * 8 + lr;
                b[0] = __float_as_uint(Bs[s][k8 * 8 + lc][col]);
                b[1] = __float_as_uint(Bs[s][k8 * 8 + lc + 4][col]);
                mma_tf32(acc[0][j], a[0], b);
                mma_tf32(acc[1][j], a[1], b);
            }
        }
    }
#pragma unroll
    for (int i = 0; i < 2; i++)
#pragma unroll
        for (int j = 0; j < 4; j++) {
            int r0 = base + wm + i * 16 + lr;
            int c0 = wn + j * 8 + lc * 2;
            if (r0 < n)
                *(float2*)(out + r0 * CH + c0) = make_float2(acc[i][j][0], acc[i][j][1]);
            if (r0 + 8 < n)
                *(float2*)(out + (r0 + 8) * CH + c0) = make_float2(acc[i][j][2], acc[i][j][3]);
        }
}

// ---------------- 5) layer2 pair GEMM: 512 thr, same core, red2 scatter ----------------
__global__ __launch_bounds__(512, 2) void k_pair_mma(float* __restrict__ out) {
    __shared__ float As[2][128][20];
    __shared__ float Bs[2][16][132];
    __shared__ int s_pin[128], s_pout[128];
    int kk = blockIdx.y;
    int k  = kk + (kk >= 13);
    int cnt = g_cnt[k]; if (cnt > MAXP) cnt = MAXP;
    const float* B = g_w2t + k * CH * CH;
    int t = threadIdx.x;
    int wid = t >> 5, lane = t & 31;
    int wm = (wid >> 2) * 32, wn = (wid & 3) * 32;
    int lr = lane >> 2, lc = lane & 3;

    for (int tile = blockIdx.x; tile * 128 < cnt; tile += gridDim.x) {
        int base = tile * 128;
        __syncthreads();                       // protect s_pin/s_pout + smem across tiles
        if (t < 128) {
            int ok = (base + t < cnt);
            s_pin [t] = ok ? g_pin [k * MAXP + base + t] : -1;
            s_pout[t] = ok ? g_pout[k * MAXP + base + t] : -1;
        }
        __syncthreads();
        float acc[2][4][4];
#pragma unroll
        for (int i = 0; i < 2; i++)
#pragma unroll
            for (int j = 0; j < 4; j++)
#pragma unroll
                for (int q = 0; q < 4; q++) acc[i][j][q] = 0.f;

        auto stage = [&](int s, int kt) {
            {   // A gather: 128 rows x 16 k = 512 float4, 1 per thread
                int row = t >> 2, c4 = t & 3;
                int m = s_pin[row];
                int mm = m < 0 ? 0 : m;
                cp16(&As[s][row][c4 * 4], g_h + mm * CH + kt * 16 + c4 * 4, m >= 0);
            }
            {   // B: 16 k x 128 cols
                int row = t >> 5, c4 = t & 31;
                cp16(&Bs[s][row][c4 * 4], B + (kt * 16 + row) * CH + c4 * 4, true);
            }
        };

        stage(0, 0);
        CP_COMMIT();
#pragma unroll 1
        for (int kt = 0; kt < 8; kt++) {
            int s = kt & 1;
            CP_WAIT0();
            __syncthreads();
            if (kt + 1 < 8) { stage(s ^ 1, kt + 1); CP_COMMIT(); }
#pragma unroll
            for (int k8 = 0; k8 < 2; k8++) {
                unsigned a[2][4];
#pragma unroll
                for (int i = 0; i < 2; i++) {
                    int r0 = wm + i * 16 + lr;
                    a[i][0] = __float_as_uint(As[s][r0][k8 * 8 + lc]);
                    a[i][1] = __float_as_uint(As[s][r0 + 8][k8 * 8 + lc]);
                    a[i][2] = __float_as_uint(As[s][r0][k8 * 8 + lc + 4]);
                    a[i][3] = __float_as_uint(As[s][r0 + 8][k8 * 8 + lc + 4]);
                }
#pragma unroll
                for (int j = 0; j < 4; j++) {
                    unsigned b[2];
                    int col = wn + j * 8 + lr;
                    b[0] = __float_as_uint(Bs[s][k8 * 8 + lc][col]);
                    b[1] = __float_as_uint(Bs[s][k8 * 8 + lc + 4][col]);
                    mma_tf32(acc[0][j], a[0], b);
                    mma_tf32(acc[1][j], a[1], b);
                }
            }
        }
        // scatter-accumulate with vector reductions
#pragma unroll
        for (int i = 0; i < 2; i++) {
            int r0 = wm + i * 16 + lr;
            int po0 = s_pout[r0];
            int po1 = s_pout[r0 + 8];
#pragma unroll
            for (int j = 0; j < 4; j++) {
                int c0 = wn + j * 8 + lc * 2;
                if (po0 >= 0) red2(out + po0 * CH + c0, acc[i][j][0], acc[i][j][1]);
                if (po1 >= 0) red2(out + po1 * CH + c0, acc[i][j][2], acc[i][j][3]);
            }
        }
    }
}

// ---------------- 6) cleanup: restore zero-state for next replay ----------------
__global__ void k_cleanup(const int* __restrict__ coors, int n) {
    int i = blockIdx.x * blockDim.x + threadIdx.x;
    if (i < n) {
        int4 c = ((const int4*)coors)[i];
        g_grid[(c.y * GH + c.z) * GW + c.w] = 0;
    }
    if (i < 27) g_cnt[i] = 0;
}

// ---------------- launch ----------------
extern "C" void kernel_launch(void* const* d_in, const int* in_sizes, int n_in,
                              void* d_out, int out_size) {
    const float* feat  = (const float*)d_in[0];   // [N,3]
    const int*   coors = (const int*)  d_in[1];   // [N,4]
    const float* w1    = (const float*)d_in[2];   // [27,3,128]
    const float* w2    = (const float*)d_in[3];   // [27,128,128]
    float* out = (float*)d_out;                   // [N,128]
    int n = in_sizes[0] / 3;

    int m0 = n > W2Q ? n : W2Q;
    k_scatter_cvt<<<(m0 + 255) / 256, 256>>>(coors, w2, n);
    k_build<<<(n + 255) / 256, 256>>>(coors, n);
    k_l1_fused<<<(n * 32 + 255) / 256, 256>>>(feat, w1, n);
    k_center_mma<<<(n + 127) / 128, 512>>>(out, n);
    {
        dim3 g(12, 26);
        k_pair_mma<<<g, 512>>>(out);
    }
    k_cleanup<<<(n + 255) / 256, 256>>>(coors, n);
}

// round 9
// speedup vs baseline: 1.0588x; 1.0588x over previous
#include <cuda_runtime.h>

// ---------------- problem constants ----------------
#define GD 32
#define GH 512
#define GW 512
#define GRID_VOX (GD * GH * GW)
#define NMAX 151552
#define MAXP 8192
#define CH 128
#define W2Q (27 * CH * CH / 4)

// ---------------- static device scratch (zero-initialized at load) ----------------
__device__ int   g_grid[GRID_VOX];          // voxel -> active index + 1 (0 = empty)
__device__ float g_h[NMAX * CH];            // layer-1 output (tf32-rounded)
__device__ int   g_cnt[27];
__device__ int   g_pin[27 * MAXP];
__device__ int   g_pout[27 * MAXP];
__device__ int   g_in_cnt[NMAX];
__device__ int   g_in[NMAX * 26];
__device__ float g_w2t[27 * CH * CH];       // tf32-rounded w2

// ---------------- helpers ----------------
__device__ __forceinline__ float tf(float x) {
    unsigned u;
    asm("cvt.rna.tf32.f32 %0, %1;" : "=r"(u) : "f"(x));
    return __uint_as_float(u);
}
__device__ __forceinline__ void mma_tf32(float* d, const unsigned* a, const unsigned* b) {
    asm volatile(
        "mma.sync.aligned.m16n8k8.row.col.f32.tf32.tf32.f32 "
        "{%0,%1,%2,%3},{%4,%5,%6,%7},{%8,%9},{%0,%1,%2,%3};"
        : "+f"(d[0]), "+f"(d[1]), "+f"(d[2]), "+f"(d[3])
        : "r"(a[0]), "r"(a[1]), "r"(a[2]), "r"(a[3]), "r"(b[0]), "r"(b[1]));
}
__device__ __forceinline__ void cp16(void* dst, const void* src, bool pred) {
    unsigned d = (unsigned)__cvta_generic_to_shared(dst);
    int sz = pred ? 16 : 0;
    asm volatile("cp.async.cg.shared.global [%0], [%1], 16, %2;\n"
                 :: "r"(d), "l"(src), "r"(sz));
}
#define CP_COMMIT() asm volatile("cp.async.commit_group;\n")
#define CP_WAIT0()  asm volatile("cp.async.wait_group 0;\n")
#define CP_WAIT1()  asm volatile("cp.async.wait_group 1;\n")
__device__ __forceinline__ void red2(float* addr, float a, float b) {
    asm volatile("red.global.add.v2.f32 [%0], {%1,%2};" :: "l"(addr), "f"(a), "f"(b) : "memory");
}

// ---------------- 1) scatter + w2 tf32 convert (merged) ----------------
__global__ void k_scatter_cvt(const int* __restrict__ coors,
                              const float* __restrict__ w2, int n) {
    int i = blockIdx.x * blockDim.x + threadIdx.x;
    if (i < n) {
        int4 c = ((const int4*)coors)[i];    // (batch, z, y, x)
        g_grid[(c.y * GH + c.z) * GW + c.w] = i + 1;
    }
    if (i < W2Q) {
        float4 v = ((const float4*)w2)[i];
        v.x = tf(v.x); v.y = tf(v.y); v.z = tf(v.z); v.w = tf(v.w);
        ((float4*)g_w2t)[i] = v;
    }
}

// ---------------- 2) rulebook: one thread per point, warp-agg atomics ----------------
__global__ void k_build(const int* __restrict__ coors, int n) {
    int nn = blockIdx.x * blockDim.x + threadIdx.x;
    bool act = (nn < n);
    int4 c = make_int4(0, 0, 0, 0);
    if (act) c = ((const int4*)coors)[nn];
    int lane = threadIdx.x & 31;
    int s = 0;
#pragma unroll
    for (int k = 0; k < 27; k++) {
        if (k == 13) continue;
        const int dz = k / 9 - 1, dy = (k / 3) % 3 - 1, dx = k % 3 - 1;
        int z = c.y + dz, y = c.z + dy, x = c.w + dx;
        int m = -1;
        if (act && (unsigned)z < GD && (unsigned)y < GH && (unsigned)x < GW)
            m = g_grid[(z * GH + y) * GW + x] - 1;
        bool valid = (m >= 0);
        unsigned mask = __ballot_sync(0xffffffffu, valid);
        if (mask) {
            int leader = __ffs(mask) - 1;
            int basec = 0;
            if (lane == leader) basec = atomicAdd(&g_cnt[k], __popc(mask));
            basec = __shfl_sync(0xffffffffu, basec, leader);
            if (valid) {
                int pos = basec + __popc(mask & ((1u << lane) - 1u));
                if (pos < MAXP) {
                    g_pin [k * MAXP + pos] = m;
                    g_pout[k * MAXP + pos] = nn;
                }
                g_in[nn * 26 + s] = (k << 18) | m;
                s++;
            }
        }
    }
    if (act) g_in_cnt[nn] = s;
}

// ---------------- 3) layer1 fused gather: 16 threads/point, 8 ch each ----------------
__global__ void k_l1_fused(const float* __restrict__ feat,
                           const float* __restrict__ w1, int n) {
    int gt = blockIdx.x * blockDim.x + threadIdx.x;
    int nn = gt >> 4;
    if (nn >= n) return;
    int c = (gt & 15) * 8;                   // 8 channels = 2 float4

    float f0 = feat[nn * 3 + 0];
    float f1 = feat[nn * 3 + 1];
    float f2 = feat[nn * 3 + 2];
    const float* wc = w1 + 13 * 3 * CH + c;
    float4 acc[2];
#pragma unroll
    for (int q = 0; q < 2; q++) {
        float4 r0 = *(const float4*)(wc + q * 4);
        float4 r1 = *(const float4*)(wc + CH + q * 4);
        float4 r2 = *(const float4*)(wc + 2 * CH + q * 4);
        acc[q].x = f0 * r0.x + f1 * r1.x + f2 * r2.x;
        acc[q].y = f0 * r0.y + f1 * r1.y + f2 * r2.y;
        acc[q].z = f0 * r0.z + f1 * r1.z + f2 * r2.z;
        acc[q].w = f0 * r0.w + f1 * r1.w + f2 * r2.w;
    }

    int cnt = g_in_cnt[nn];
    for (int s = 0; s < cnt; s++) {
        int packed = g_in[nn * 26 + s];
        int k = packed >> 18;
        int m = packed & 0x3FFFF;
        float g0 = feat[m * 3 + 0];
        float g1 = feat[m * 3 + 1];
        float g2 = feat[m * 3 + 2];
        const float* w = w1 + k * 3 * CH + c;
#pragma unroll
        for (int q = 0; q < 2; q++) {
            float4 q0 = *(const float4*)(w + q * 4);
            float4 q1 = *(const float4*)(w + CH + q * 4);
            float4 q2 = *(const float4*)(w + 2 * CH + q * 4);
            acc[q].x += g0 * q0.x + g1 * q1.x + g2 * q2.x;
            acc[q].y += g0 * q0.y + g1 * q1.y + g2 * q2.y;
            acc[q].z += g0 * q0.z + g1 * q1.z + g2 * q2.z;
            acc[q].w += g0 * q0.w + g1 * q1.w + g2 * q2.w;
        }
    }
#pragma unroll
    for (int q = 0; q < 2; q++) {
        acc[q].x = tf(acc[q].x); acc[q].y = tf(acc[q].y);
        acc[q].z = tf(acc[q].z); acc[q].w = tf(acc[q].w);
        *(float4*)(g_h + nn * CH + c + q * 4) = acc[q];
    }
}

// ---------------- 4) layer2 center GEMM: R3-measured-best config (45.95us) ----------------
// 128x128 tile, 256 threads = 8 warps (4m x 2n), warp tile 32x64, K chunk 16.
__global__ __launch_bounds__(256) void k_center_mma(float* __restrict__ out, int n) {
    __shared__ float As[2][128][20];
    __shared__ float Bs[2][16][132];
    const float* B = g_w2t + 13 * CH * CH;
    int t = threadIdx.x;
    int wid = t >> 5, lane = t & 31;
    int wm = (wid >> 1) * 32, wn = (wid & 1) * 64;
    int lr = lane >> 2, lc = lane & 3;
    int base = blockIdx.x * 128;
    float acc[2][8][4];
#pragma unroll
    for (int i = 0; i < 2; i++)
#pragma unroll
        for (int j = 0; j < 8; j++)
#pragma unroll
            for (int q = 0; q < 4; q++) acc[i][j][q] = 0.f;

    auto stage = [&](int s, int kt) {
#pragma unroll
        for (int q = 0; q < 2; q++) {
            int idx = t + q * 256;               // 512 float4 slots for A
            int row = idx >> 2, c4 = idx & 3;
            int gr = base + row;
            cp16(&As[s][row][c4 * 4], g_h + gr * CH + kt * 16 + c4 * 4, gr < n);
        }
#pragma unroll
        for (int q = 0; q < 2; q++) {
            int idx = t + q * 256;               // 512 float4 slots for B
            int row = idx >> 5, c4 = idx & 31;
            cp16(&Bs[s][row][c4 * 4], B + (kt * 16 + row) * CH + c4 * 4, true);
        }
    };

    stage(0, 0);
    CP_COMMIT();
#pragma unroll 1
    for (int kt = 0; kt < 8; kt++) {
        int s = kt & 1;
        if (kt + 1 < 8) { stage(s ^ 1, kt + 1); CP_COMMIT(); CP_WAIT1(); }
        else           { CP_WAIT0(); }
        __syncthreads();
#pragma unroll
        for (int k8 = 0; k8 < 2; k8++) {
            unsigned a[2][4];
#pragma unroll
            for (int i = 0; i < 2; i++) {
                int r0 = wm + i * 16 + lr;
                a[i][0] = __float_as_uint(As[s][r0][k8 * 8 + lc]);
                a[i][1] = __float_as_uint(As[s][r0 + 8][k8 * 8 + lc]);
                a[i][2] = __float_as_uint(As[s][r0][k8 * 8 + lc + 4]);
                a[i][3] = __float_as_uint(As[s][r0 + 8][k8 * 8 + lc + 4]);
            }
#pragma unroll
            for (int j = 0; j < 8; j++) {
                unsigned b[2];
                int col = wn + j * 8 + lr;
                b[0] = __float_as_uint(Bs[s][k8 * 8 + lc][col]);
                b[1] = __float_as_uint(Bs[s][k8 * 8 + lc + 4][col]);
                mma_tf32(acc[0][j], a[0], b);
                mma_tf32(acc[1][j], a[1], b);
            }
        }
        __syncthreads();
    }
#pragma unroll
    for (int i = 0; i < 2; i++)
#pragma unroll
        for (int j = 0; j < 8; j++) {
            int r0 = base + wm + i * 16 + lr;
            int c0 = wn + j * 8 + lc * 2;
            if (r0 < n)
                *(float2*)(out + r0 * CH + c0) = make_float2(acc[i][j][0], acc[i][j][1]);
            if (r0 + 8 < n)
                *(float2*)(out + (r0 + 8) * CH + c0) = make_float2(acc[i][j][2], acc[i][j][3]);
        }
}

// ---------------- 5) layer2 pair GEMM: R3 config, single-wave grid ----------------
__global__ __launch_bounds__(256) void k_pair_mma(float* __restrict__ out) {
    __shared__ float As[2][128][20];
    __shared__ float Bs[2][16][132];
    __shared__ int s_pin[128], s_pout[128];
    int kk = blockIdx.y;
    int k  = kk + (kk >= 13);
    int cnt = g_cnt[k]; if (cnt > MAXP) cnt = MAXP;
    const float* B = g_w2t + k * CH * CH;
    int t = threadIdx.x;
    int wid = t >> 5, lane = t & 31;
    int wm = (wid >> 1) * 32, wn = (wid & 1) * 64;
    int lr = lane >> 2, lc = lane & 3;

    for (int tile = blockIdx.x; tile * 128 < cnt; tile += gridDim.x) {
        int base = tile * 128;
        __syncthreads();
        if (t < 128) {
            int ok = (base + t < cnt);
            s_pin [t] = ok ? g_pin [k * MAXP + base + t] : -1;
            s_pout[t] = ok ? g_pout[k * MAXP + base + t] : -1;
        }
        __syncthreads();
        float acc[2][8][4];
#pragma unroll
        for (int i = 0; i < 2; i++)
#pragma unroll
            for (int j = 0; j < 8; j++)
#pragma unroll
                for (int q = 0; q < 4; q++) acc[i][j][q] = 0.f;

        auto stage = [&](int s, int kt) {
#pragma unroll
            for (int q = 0; q < 2; q++) {
                int idx = t + q * 256;
                int row = idx >> 2, c4 = idx & 3;
                int m = s_pin[row];
                int mm = m < 0 ? 0 : m;
                cp16(&As[s][row][c4 * 4], g_h + mm * CH + kt * 16 + c4 * 4, m >= 0);
            }
#pragma unroll
            for (int q = 0; q < 2; q++) {
                int idx = t + q * 256;
                int row = idx >> 5, c4 = idx & 31;
                cp16(&Bs[s][row][c4 * 4], B + (kt * 16 + row) * CH + c4 * 4, true);
            }
        };

        stage(0, 0);
        CP_COMMIT();
#pragma unroll 1
        for (int kt = 0; kt < 8; kt++) {
            int s = kt & 1;
            if (kt + 1 < 8) { stage(s ^ 1, kt + 1); CP_COMMIT(); CP_WAIT1(); }
            else           { CP_WAIT0(); }
            __syncthreads();
#pragma unroll
            for (int k8 = 0; k8 < 2; k8++) {
                unsigned a[2][4];
#pragma unroll
                for (int i = 0; i < 2; i++) {
                    int r0 = wm + i * 16 + lr;
                    a[i][0] = __float_as_uint(As[s][r0][k8 * 8 + lc]);
                    a[i][1] = __float_as_uint(As[s][r0 + 8][k8 * 8 + lc]);
                    a[i][2] = __float_as_uint(As[s][r0][k8 * 8 + lc + 4]);
                    a[i][3] = __float_as_uint(As[s][r0 + 8][k8 * 8 + lc + 4]);
                }
#pragma unroll
                for (int j = 0; j < 8; j++) {
                    unsigned b[2];
                    int col = wn + j * 8 + lr;
                    b[0] = __float_as_uint(Bs[s][k8 * 8 + lc][col]);
                    b[1] = __float_as_uint(Bs[s][k8 * 8 + lc + 4][col]);
                    mma_tf32(acc[0][j], a[0], b);
                    mma_tf32(acc[1][j], a[1], b);
                }
            }
            __syncthreads();
        }
        // scatter-accumulate with vector reductions
#pragma unroll
        for (int i = 0; i < 2; i++) {
            int r0 = wm + i * 16 + lr;
            int po0 = s_pout[r0];
            int po1 = s_pout[r0 + 8];
#pragma unroll
            for (int j = 0; j < 8; j++) {
                int c0 = wn + j * 8 + lc * 2;
                if (po0 >= 0) red2(out + po0 * CH + c0, acc[i][j][0], acc[i][j][1]);
                if (po1 >= 0) red2(out + po1 * CH + c0, acc[i][j][2], acc[i][j][3]);
            }
        }
    }
}

// ---------------- 6) cleanup: restore zero-state for next replay ----------------
__global__ void k_cleanup(const int* __restrict__ coors, int n) {
    int i = blockIdx.x * blockDim.x + threadIdx.x;
    if (i < n) {
        int4 c = ((const int4*)coors)[i];
        g_grid[(c.y * GH + c.z) * GW + c.w] = 0;
    }
    if (i < 27) g_cnt[i] = 0;
}

// ---------------- launch ----------------
extern "C" void kernel_launch(void* const* d_in, const int* in_sizes, int n_in,
                              void* d_out, int out_size) {
    const float* feat  = (const float*)d_in[0];   // [N,3]
    const int*   coors = (const int*)  d_in[1];   // [N,4]
    const float* w1    = (const float*)d_in[2];   // [27,3,128]
    const float* w2    = (const float*)d_in[3];   // [27,128,128]
    float* out = (float*)d_out;                   // [N,128]
    int n = in_sizes[0] / 3;

    int m0 = n > W2Q ? n : W2Q;
    k_scatter_cvt<<<(m0 + 255) / 256, 256>>>(coors, w2, n);
    k_build<<<(n + 255) / 256, 256>>>(coors, n);
    k_l1_fused<<<(n * 16 + 255) / 256, 256>>>(feat, w1, n);
    k_center_mma<<<(n + 127) / 128, 256>>>(out, n);
    {
        dim3 g(11, 26);   // 286 CTAs <= 296 capacity at 2 CTA/SM -> single wave
        k_pair_mma<<<g, 256>>>(out);
    }
    k_cleanup<<<(n + 255) / 256, 256>>>(coors, n);
}

// round 11
// speedup vs baseline: 1.2075x; 1.1404x over previous
#include <cuda_runtime.h>
#include <cuda_fp16.h>
#include <cstdint>

// ---------------- problem constants ----------------
#define GD 32
#define GH 512
#define GW 512
#define GRID_VOX (GD * GH * GW)
#define NMAX 151552
#define MAXP 8192
#define CH 128
#define W2E (27 * CH * CH)          // elements of w2

// ---------------- static device scratch (zero-initialized at load) ----------------
__device__ int    g_grid[GRID_VOX];         // voxel -> active index + 1 (0 = empty)
__device__ __half g_h[NMAX * CH];           // layer-1 output (fp16)
__device__ int    g_cnt[27];
__device__ int    g_pin[27 * MAXP];
__device__ int    g_pout[27 * MAXP];
__device__ int    g_in_cnt[NMAX];
__device__ int    g_in[NMAX * 26];
__device__ __half g_w2h[W2E];               // w2 transposed per offset: [k][co][ci], fp16

// ---------------- helpers ----------------
__device__ __forceinline__ void mma_f16(float* d, const unsigned* a, const unsigned* b) {
    asm volatile(
        "mma.sync.aligned.m16n8k16.row.col.f32.f16.f16.f32 "
        "{%0,%1,%2,%3},{%4,%5,%6,%7},{%8,%9},{%0,%1,%2,%3};"
        : "+f"(d[0]), "+f"(d[1]), "+f"(d[2]), "+f"(d[3])
        : "r"(a[0]), "r"(a[1]), "r"(a[2]), "r"(a[3]), "r"(b[0]), "r"(b[1]));
}
__device__ __forceinline__ void cp16(void* dst, const void* src, bool pred) {
    unsigned d = (unsigned)__cvta_generic_to_shared(dst);
    int sz = pred ? 16 : 0;
    asm volatile("cp.async.cg.shared.global [%0], [%1], 16, %2;\n"
                 :: "r"(d), "l"(src), "r"(sz));
}
#define CP_COMMIT() asm volatile("cp.async.commit_group;\n")
#define CP_WAIT0()  asm volatile("cp.async.wait_group 0;\n")
#define CP_WAIT1()  asm volatile("cp.async.wait_group 1;\n")
__device__ __forceinline__ void red2(float* addr, float a, float b) {
    asm volatile("red.global.add.v2.f32 [%0], {%1,%2};" :: "l"(addr), "f"(a), "f"(b) : "memory");
}

// ---------------- 1) scatter + w2 fp16 transpose-convert (merged) ----------------
__global__ void k_scatter_cvt(const int* __restrict__ coors,
                              const float* __restrict__ w2, int n) {
    int i = blockIdx.x * blockDim.x + threadIdx.x;
    if (i < n) {
        int4 c = ((const int4*)coors)[i];    // (batch, z, y, x)
        g_grid[(c.y * GH + c.z) * GW + c.w] = i + 1;
    }
    if (i < W2E) {                           // g_w2h[k][co][ci] = w2[k][ci][co]
        int k  = i >> 14;
        int r  = i & 16383;
        int co = r >> 7, ci = r & 127;
        g_w2h[i] = __float2half_rn(w2[(k << 14) + ci * CH + co]);
    }
}

// ---------------- 2) rulebook: one thread per point, warp-agg atomics ----------------
__global__ void k_build(const int* __restrict__ coors, int n) {
    int nn = blockIdx.x * blockDim.x + threadIdx.x;
    bool act = (nn < n);
    int4 c = make_int4(0, 0, 0, 0);
    if (act) c = ((const int4*)coors)[nn];
    int lane = threadIdx.x & 31;
    int s = 0;
#pragma unroll
    for (int k = 0; k < 27; k++) {
        if (k == 13) continue;
        const int dz = k / 9 - 1, dy = (k / 3) % 3 - 1, dx = k % 3 - 1;
        int z = c.y + dz, y = c.z + dy, x = c.w + dx;
        int m = -1;
        if (act && (unsigned)z < GD && (unsigned)y < GH && (unsigned)x < GW)
            m = g_grid[(z * GH + y) * GW + x] - 1;
        bool valid = (m >= 0);
        unsigned mask = __ballot_sync(0xffffffffu, valid);
        if (mask) {
            int leader = __ffs(mask) - 1;
            int basec = 0;
            if (lane == leader) basec = atomicAdd(&g_cnt[k], __popc(mask));
            basec = __shfl_sync(0xffffffffu, basec, leader);
            if (valid) {
                int pos = basec + __popc(mask & ((1u << lane) - 1u));
                if (pos < MAXP) {
                    g_pin [k * MAXP + pos] = m;
                    g_pout[k * MAXP + pos] = nn;
                }
                g_in[nn * 26 + s] = (k << 18) | m;
                s++;
            }
        }
    }
    if (act) g_in_cnt[nn] = s;
}

// ---------------- 3) layer1 fused gather: 32 threads/point, 4 ch each, fp16 out ----------------
__global__ void k_l1_fused(const float* __restrict__ feat,
                           const float* __restrict__ w1, int n) {
    int gt = blockIdx.x * blockDim.x + threadIdx.x;
    int nn = gt >> 5;
    if (nn >= n) return;
    int c = (gt & 31) * 4;

    float f0 = feat[nn * 3 + 0];
    float f1 = feat[nn * 3 + 1];
    float f2 = feat[nn * 3 + 2];
    const float* wc = w1 + 13 * 3 * CH;
    float4 r0 = *(const float4*)(wc + c);
    float4 r1 = *(const float4*)(wc + CH + c);
    float4 r2 = *(const float4*)(wc + 2 * CH + c);
    float4 acc;
    acc.x = f0 * r0.x + f1 * r1.x + f2 * r2.x;
    acc.y = f0 * r0.y + f1 * r1.y + f2 * r2.y;
    acc.z = f0 * r0.z + f1 * r1.z + f2 * r2.z;
    acc.w = f0 * r0.w + f1 * r1.w + f2 * r2.w;

    int cnt = g_in_cnt[nn];
    for (int s = 0; s < cnt; s++) {
        int packed = g_in[nn * 26 + s];
        int k = packed >> 18;
        int m = packed & 0x3FFFF;
        float g0 = feat[m * 3 + 0];
        float g1 = feat[m * 3 + 1];
        float g2 = feat[m * 3 + 2];
        const float* w = w1 + k * 3 * CH;
        float4 q0 = *(const float4*)(w + c);
        float4 q1 = *(const float4*)(w + CH + c);
        float4 q2 = *(const float4*)(w + 2 * CH + c);
        acc.x += g0 * q0.x + g1 * q1.x + g2 * q2.x;
        acc.y += g0 * q0.y + g1 * q1.y + g2 * q2.y;
        acc.z += g0 * q0.z + g1 * q1.z + g2 * q2.z;
        acc.w += g0 * q0.w + g1 * q1.w + g2 * q2.w;
    }
    __half2 h0 = __floats2half2_rn(acc.x, acc.y);
    __half2 h1 = __floats2half2_rn(acc.z, acc.w);
    *(__half2*)(g_h + nn * CH + c)     = h0;
    *(__half2*)(g_h + nn * CH + c + 2) = h1;
}

// ---------------- 4) layer2 center GEMM: fp16 m16n8k16, R4 pipeline ----------------
// 128x128 tile, 256 threads = 8 warps (4m x 2n), warp tile 32x64, K chunk 16.
__global__ __launch_bounds__(256) void k_center_mma(float* __restrict__ out, int n) {
    __shared__ __half As[2][128][24];        // [row][k] halfs
    __shared__ __half Bs[2][128][24];        // [col][k] halfs (B transposed)
    const __half* B = g_w2h + 13 * CH * CH;  // [co][ci]
    int t = threadIdx.x;
    int wid = t >> 5, lane = t & 31;
    int wm = (wid >> 1) * 32, wn = (wid & 1) * 64;
    int lr = lane >> 2, lc = lane & 3;
    int base = blockIdx.x * 128;
    float acc[2][8][4];
#pragma unroll
    for (int i = 0; i < 2; i++)
#pragma unroll
        for (int j = 0; j < 8; j++)
#pragma unroll
            for (int q = 0; q < 4; q++) acc[i][j][q] = 0.f;

    auto stage = [&](int s, int kt) {
        int row = t >> 1, hc = (t & 1) * 8;  // 128 rows x 2 16B-chunks
        int gr = base + row;
        cp16(&As[s][row][hc], g_h + (size_t)gr * CH + kt * 16 + hc, gr < n);
        cp16(&Bs[s][row][hc], B + (size_t)row * CH + kt * 16 + hc, true);
    };

    stage(0, 0);
    CP_COMMIT();
#pragma unroll 1
    for (int kt = 0; kt < 8; kt++) {
        int s = kt & 1;
        if (kt + 1 < 8) { stage(s ^ 1, kt + 1); CP_COMMIT(); CP_WAIT1(); }
        else           { CP_WAIT0(); }
        __syncthreads();
        unsigned a[2][4];
#pragma unroll
        for (int i = 0; i < 2; i++) {
            int r0 = wm + i * 16 + lr;
            a[i][0] = *(const unsigned*)&As[s][r0][lc * 2];
            a[i][1] = *(const unsigned*)&As[s][r0 + 8][lc * 2];
            a[i][2] = *(const unsigned*)&As[s][r0][lc * 2 + 8];
            a[i][3] = *(const unsigned*)&As[s][r0 + 8][lc * 2 + 8];
        }
#pragma unroll
        for (int j = 0; j < 8; j++) {
            int col = wn + j * 8 + lr;
            unsigned b[2];
            b[0] = *(const unsigned*)&Bs[s][col][lc * 2];
            b[1] = *(const unsigned*)&Bs[s][col][lc * 2 + 8];
            mma_f16(acc[0][j], a[0], b);
            mma_f16(acc[1][j], a[1], b);
        }
        __syncthreads();
    }
#pragma unroll
    for (int i = 0; i < 2; i++)
#pragma unroll
        for (int j = 0; j < 8; j++) {
            int r0 = base + wm + i * 16 + lr;
            int c0 = wn + j * 8 + lc * 2;
            if (r0 < n)
                *(float2*)(out + (size_t)r0 * CH + c0) = make_float2(acc[i][j][0], acc[i][j][1]);
            if (r0 + 8 < n)
                *(float2*)(out + (size_t)(r0 + 8) * CH + c0) = make_float2(acc[i][j][2], acc[i][j][3]);
        }
}

// ---------------- 5) layer2 pair GEMM: fp16 m16n8k16, red2 scatter ----------------
__global__ __launch_bounds__(256) void k_pair_mma(float* __restrict__ out) {
    __shared__ __half As[2][128][24];
    __shared__ __half Bs[2][128][24];
    __shared__ int s_pin[128], s_pout[128];
    int kk = blockIdx.y;
    int k  = kk + (kk >= 13);
    int cnt = g_cnt[k]; if (cnt > MAXP) cnt = MAXP;
    const __half* B = g_w2h + (size_t)k * CH * CH;
    int t = threadIdx.x;
    int wid = t >> 5, lane = t & 31;
    int wm = (wid >> 1) * 32, wn = (wid & 1) * 64;
    int lr = lane >> 2, lc = lane & 3;

    for (int tile = blockIdx.x; tile * 128 < cnt; tile += gridDim.x) {
        int base = tile * 128;
        __syncthreads();
        if (t < 128) {
            int ok = (base + t < cnt);
            s_pin [t] = ok ? g_pin [k * MAXP + base + t] : -1;
            s_pout[t] = ok ? g_pout[k * MAXP + base + t] : -1;
        }
        __syncthreads();
        float acc[2][8][4];
#pragma unroll
        for (int i = 0; i < 2; i++)
#pragma unroll
            for (int j = 0; j < 8; j++)
#pragma unroll
                for (int q = 0; q < 4; q++) acc[i][j][q] = 0.f;

        auto stage = [&](int s, int kt) {
            int row = t >> 1, hc = (t & 1) * 8;
            int m = s_pin[row];
            int mm = m < 0 ? 0 : m;
            cp16(&As[s][row][hc], g_h + (size_t)mm * CH + kt * 16 + hc, m >= 0);
            cp16(&Bs[s][row][hc], B + (size_t)row * CH + kt * 16 + hc, true);
        };

        stage(0, 0);
        CP_COMMIT();
#pragma unroll 1
        for (int kt = 0; kt < 8; kt++) {
            int s = kt & 1;
            if (kt + 1 < 8) { stage(s ^ 1, kt + 1); CP_COMMIT(); CP_WAIT1(); }
            else           { CP_WAIT0(); }
            __syncthreads();
            unsigned a[2][4];
#pragma unroll
            for (int i = 0; i < 2; i++) {
                int r0 = wm + i * 16 + lr;
                a[i][0] = *(const unsigned*)&As[s][r0][lc * 2];
                a[i][1] = *(const unsigned*)&As[s][r0 + 8][lc * 2];
                a[i][2] = *(const unsigned*)&As[s][r0][lc * 2 + 8];
                a[i][3] = *(const unsigned*)&As[s][r0 + 8][lc * 2 + 8];
            }
#pragma unroll
            for (int j = 0; j < 8; j++) {
                int col = wn + j * 8 + lr;
                unsigned b[2];
                b[0] = *(const unsigned*)&Bs[s][col][lc * 2];
                b[1] = *(const unsigned*)&Bs[s][col][lc * 2 + 8];
                mma_f16(acc[0][j], a[0], b);
                mma_f16(acc[1][j], a[1], b);
            }
            __syncthreads();
        }
        // scatter-accumulate with vector reductions
#pragma unroll
        for (int i = 0; i < 2; i++) {
            int r0 = wm + i * 16 + lr;
            int po0 = s_pout[r0];
            int po1 = s_pout[r0 + 8];
#pragma unroll
            for (int j = 0; j < 8; j++) {
                int c0 = wn + j * 8 + lc * 2;
                if (po0 >= 0) red2(out + (size_t)po0 * CH + c0, acc[i][j][0], acc[i][j][1]);
                if (po1 >= 0) red2(out + (size_t)po1 * CH + c0, acc[i][j][2], acc[i][j][3]);
            }
        }
    }
}

// ---------------- 6) cleanup: restore zero-state for next replay ----------------
__global__ void k_cleanup(const int* __restrict__ coors, int n) {
    int i = blockIdx.x * blockDim.x + threadIdx.x;
    if (i < n) {
        int4 c = ((const int4*)coors)[i];
        g_grid[(c.y * GH + c.z) * GW + c.w] = 0;
    }
    if (i < 27) g_cnt[i] = 0;
}

// ---------------- launch ----------------
extern "C" void kernel_launch(void* const* d_in, const int* in_sizes, int n_in,
                              void* d_out, int out_size) {
    const float* feat  = (const float*)d_in[0];   // [N,3]
    const int*   coors = (const int*)  d_in[1];   // [N,4]
    const float* w1    = (const float*)d_in[2];   // [27,3,128]
    const float* w2    = (const float*)d_in[3];   // [27,128,128]
    float* out = (float*)d_out;                   // [N,128]
    int n = in_sizes[0] / 3;

    int m0 = n > W2E ? n : W2E;
    k_scatter_cvt<<<(m0 + 255) / 256, 256>>>(coors, w2, n);
    k_build<<<(n + 255) / 256, 256>>>(coors, n);
    k_l1_fused<<<(n * 32 + 255) / 256, 256>>>(feat, w1, n);
    k_center_mma<<<(n + 127) / 128, 256>>>(out, n);
    {
        dim3 g(24, 26);
        k_pair_mma<<<g, 256>>>(out);
    }
    k_cleanup<<<(n + 255) / 256, 256>>>(coors, n);
}